// round 3
// baseline (speedup 1.0000x reference)
#include <cuda_runtime.h>
#include <math.h>

// ---------------- problem constants ----------------
#define C_DIM 768
#define NQ    13824      // 24^3 queries
#define NKV   1728       // 12^3 keys/values after SR
#define NH    8
#define HD    96
#define KCONV 6144       // 768 * 2*2*2
#define ALPHA_SCORE 0.35355339059327373f   // 1/sqrt(8)  (ref divides by sqrt(num_heads))

// ---------------- scratch (device globals; no allocation allowed) ----------------
__device__ float g_q   [(size_t)NQ  * C_DIM];        // 42.5 MB
__device__ float g_col [(size_t)NKV * KCONV];        // 42.5 MB
__device__ float g_xr  [(size_t)NKV * C_DIM];        //  5.3 MB
__device__ float g_kv  [(size_t)NKV * 2 * C_DIM];    // 10.6 MB
__device__ float g_s   [(size_t)NQ  * NKV];          // 95.5 MB (reused per head)
__device__ float g_attn[(size_t)NQ  * C_DIM];        // 42.5 MB

// ---------------- generic tiled SGEMM ----------------
// C[M,N] = alpha * A[M,K] @ B + bias(col)    (B is [K,N] or, if TRANSB, [N,K])
// BM=BN=128, BK=8, 256 threads, 8x8 per-thread tile.
#define BM 128
#define BN 128
#define BK 8
#define TM 8
#define TN 8

template <bool TRANSB>
__global__ __launch_bounds__(256) void sgemm(
    const float* __restrict__ A, const float* __restrict__ B,
    float* __restrict__ C, const float* __restrict__ bias,
    float alpha, int M, int N, int K, int lda, int ldb, int ldc)
{
    __shared__ float As[BK][BM];
    __shared__ float Bs[BK][BN];

    const int m0 = blockIdx.y * BM;
    const int n0 = blockIdx.x * BN;
    const int tid = threadIdx.x;
    const int tx = tid & 15;   // 0..15 (col group)
    const int ty = tid >> 4;   // 0..15 (row group)

    float acc[TM][TN];
#pragma unroll
    for (int i = 0; i < TM; ++i)
#pragma unroll
        for (int j = 0; j < TN; ++j) acc[i][j] = 0.f;

    // A tile loader: each thread one float4. row = tid>>1 (0..127), col4 = (tid&1)*4
    const int arow  = tid >> 1;
    const int acol4 = (tid & 1) * 4;
    // B (non-trans) loader: k-row = tid>>5 (0..7), n-col4 = (tid&31)*4
    const int brow  = tid >> 5;
    const int bcol4 = (tid & 31) * 4;

    for (int k0 = 0; k0 < K; k0 += BK) {
        // ---- load A tile (transposed into As[k][m]) ----
        {
            float4 av = make_float4(0.f, 0.f, 0.f, 0.f);
            const int gm = m0 + arow;
            if (gm < M)
                av = *(const float4*)(A + (long long)gm * lda + k0 + acol4);
            As[acol4 + 0][arow] = av.x;
            As[acol4 + 1][arow] = av.y;
            As[acol4 + 2][arow] = av.z;
            As[acol4 + 3][arow] = av.w;
        }
        // ---- load B tile ----
        if (TRANSB) {
            float4 bv = make_float4(0.f, 0.f, 0.f, 0.f);
            const int gn = n0 + arow;
            if (gn < N)
                bv = *(const float4*)(B + (long long)gn * ldb + k0 + acol4);
            Bs[acol4 + 0][arow] = bv.x;
            Bs[acol4 + 1][arow] = bv.y;
            Bs[acol4 + 2][arow] = bv.z;
            Bs[acol4 + 3][arow] = bv.w;
        } else {
            float4 bv = make_float4(0.f, 0.f, 0.f, 0.f);
            const int gn = n0 + bcol4;
            const int gk = k0 + brow;          // K is always a multiple of 8 here
            if (gn < N)                        // N is always a multiple of 4 here
                bv = *(const float4*)(B + (long long)gk * ldb + gn);
            *(float4*)&Bs[brow][bcol4] = bv;
        }
        __syncthreads();

        // ---- compute ----
#pragma unroll
        for (int kk = 0; kk < BK; ++kk) {
            float a[TM], b[TN];
#pragma unroll
            for (int i = 0; i < TM; ++i) a[i] = As[kk][ty * TM + i];
#pragma unroll
            for (int j = 0; j < TN; ++j) b[j] = Bs[kk][tx * TN + j];
#pragma unroll
            for (int i = 0; i < TM; ++i)
#pragma unroll
                for (int j = 0; j < TN; ++j)
                    acc[i][j] = fmaf(a[i], b[j], acc[i][j]);
        }
        __syncthreads();
    }

    // ---- epilogue ----
    const int row0 = m0 + ty * TM;
    const int col0 = n0 + tx * TN;
#pragma unroll
    for (int i = 0; i < TM; ++i) {
        const int r = row0 + i;
        if (r >= M) continue;
#pragma unroll
        for (int j = 0; j < TN; ++j) {
            const int c = col0 + j;
            if (c >= N) continue;
            float v = acc[i][j] * alpha;
            if (bias) v += bias[c];
            C[(long long)r * ldc + c] = v;
        }
    }
}

// ---------------- im2col for SR conv (kernel=stride=2, non-overlapping) ----------------
// col[p][ci*8 + dz*4+dy*2+dx] = x[ ((2pz+dz)*24 + (2py+dy))*24 + (2px+dx) ][ci]
__global__ void im2col_kernel(const float* __restrict__ x, float* __restrict__ col)
{
    const long long idx = (long long)blockIdx.x * blockDim.x + threadIdx.x;
    if (idx >= (long long)NKV * KCONV) return;
    const int p = (int)(idx / KCONV);
    const int r = (int)(idx - (long long)p * KCONV);
    const int ci = r >> 3;
    const int corner = r & 7;
    const int dz = corner >> 2, dy = (corner >> 1) & 1, dx = corner & 1;
    const int pz = p / 144;
    const int rem = p - pz * 144;
    const int py = rem / 12;
    const int px = rem - py * 12;
    const int pos = ((2 * pz + dz) * 24 + (2 * py + dy)) * 24 + (2 * px + dx);
    col[idx] = x[(size_t)pos * C_DIM + ci];
}

// ---------------- row LayerNorm over C (population var), in-place ----------------
__global__ void ln_kernel(float* __restrict__ X,
                          const float* __restrict__ g, const float* __restrict__ b)
{
    const int r = blockIdx.x;
    float* row = X + (size_t)r * C_DIM;
    __shared__ float s1[256], s2[256];
    const int t = threadIdx.x;
    float sum = 0.f, sq = 0.f;
    for (int i = t; i < C_DIM; i += 256) { float v = row[i]; sum += v; sq += v * v; }
    s1[t] = sum; s2[t] = sq;
    __syncthreads();
    for (int st = 128; st > 0; st >>= 1) {
        if (t < st) { s1[t] += s1[t + st]; s2[t] += s2[t + st]; }
        __syncthreads();
    }
    const float mu  = s1[0] * (1.f / C_DIM);
    const float var = s2[0] * (1.f / C_DIM) - mu * mu;
    const float inv = rsqrtf(var + 1e-5f);
    for (int i = t; i < C_DIM; i += 256)
        row[i] = (row[i] - mu) * inv * g[i] + b[i];
}

// ---------------- row softmax over NKV, in-place ----------------
__global__ void softmax_kernel(float* __restrict__ S)
{
    const int r = blockIdx.x;
    float* row = S + (size_t)r * NKV;
    __shared__ float red[256];
    const int t = threadIdx.x;
    float m = -1e30f;
    for (int i = t; i < NKV; i += 256) m = fmaxf(m, row[i]);
    red[t] = m;
    __syncthreads();
    for (int st = 128; st > 0; st >>= 1) {
        if (t < st) red[t] = fmaxf(red[t], red[t + st]);
        __syncthreads();
    }
    m = red[0];
    __syncthreads();
    float sum = 0.f;
    for (int i = t; i < NKV; i += 256) {
        float e = __expf(row[i] - m);
        row[i] = e;
        sum += e;
    }
    red[t] = sum;
    __syncthreads();
    for (int st = 128; st > 0; st >>= 1) {
        if (t < st) red[t] += red[t + st];
        __syncthreads();
    }
    const float inv = 1.f / red[0];
    for (int i = t; i < NKV; i += 256) row[i] *= inv;
}

// ---------------- launch ----------------
extern "C" void kernel_launch(void* const* d_in, const int* in_sizes, int n_in,
                              void* d_out, int out_size)
{
    const float* x      = (const float*)d_in[0];
    const float* wq     = (const float*)d_in[1];
    const float* wkv    = (const float*)d_in[2];
    const float* sr_w   = (const float*)d_in[3];
    const float* sr_b   = (const float*)d_in[4];
    const float* ln_g   = (const float*)d_in[5];
    const float* ln_b   = (const float*)d_in[6];
    const float* proj_w = (const float*)d_in[7];
    const float* proj_b = (const float*)d_in[8];
    float* out = (float*)d_out;

    float *q, *col, *xr, *kv, *s, *attn;
    cudaGetSymbolAddress((void**)&q,    g_q);
    cudaGetSymbolAddress((void**)&col,  g_col);
    cudaGetSymbolAddress((void**)&xr,   g_xr);
    cudaGetSymbolAddress((void**)&kv,   g_kv);
    cudaGetSymbolAddress((void**)&s,    g_s);
    cudaGetSymbolAddress((void**)&attn, g_attn);

    const dim3 blk(256);

    // 1) Q = x @ wq                       [13824,768] x [768,768]
    sgemm<false><<<dim3(C_DIM / BN, NQ / BM), blk>>>(
        x, wq, q, nullptr, 1.f, NQ, C_DIM, C_DIM, C_DIM, C_DIM, C_DIM);

    // 2) im2col for SR conv
    {
        long long tot = (long long)NKV * KCONV;
        im2col_kernel<<<(unsigned)((tot + 255) / 256), blk>>>(x, col);
    }

    // 3) conv-as-GEMM: xr = col @ sr_w^T + sr_b    [1728,6144] x [768,6144]^T
    sgemm<true><<<dim3(C_DIM / BN, (NKV + BM - 1) / BM), blk>>>(
        col, sr_w, xr, sr_b, 1.f, NKV, C_DIM, KCONV, KCONV, KCONV, C_DIM);

    // 4) LayerNorm rows of xr
    ln_kernel<<<NKV, blk>>>(xr, ln_g, ln_b);

    // 5) KV = xr @ wkv                    [1728,768] x [768,1536]
    sgemm<false><<<dim3(2 * C_DIM / BN, (NKV + BM - 1) / BM), blk>>>(
        xr, wkv, kv, nullptr, 1.f, NKV, 2 * C_DIM, C_DIM, C_DIM, 2 * C_DIM, 2 * C_DIM);

    // 6) per-head attention (scores buffer reused)
    for (int h = 0; h < NH; ++h) {
        // scores = (q_h @ k_h^T) / sqrt(8)   [13824,96] x [1728,96]^T
        sgemm<true><<<dim3((NKV + BN - 1) / BN, NQ / BM), blk>>>(
            q + h * HD, kv + h * HD, s, nullptr, ALPHA_SCORE,
            NQ, NKV, HD, C_DIM, 2 * C_DIM, NKV);
        // softmax rows
        softmax_kernel<<<NQ, blk>>>(s);
        // attn_h = probs @ v_h               [13824,1728] x [1728,96]
        sgemm<false><<<dim3(1, NQ / BM), blk>>>(
            s, kv + C_DIM + h * HD, attn + h * HD, nullptr, 1.f,
            NQ, HD, NKV, NKV, 2 * C_DIM, C_DIM);
    }

    // 7) out = attn @ proj_w + proj_b      [13824,768] x [768,768]
    sgemm<false><<<dim3(C_DIM / BN, NQ / BM), blk>>>(
        attn, proj_w, out, proj_b, 1.f, NQ, C_DIM, C_DIM, C_DIM, C_DIM, C_DIM);
}

// round 4
// speedup vs baseline: 2.4845x; 2.4845x over previous
#include <cuda_runtime.h>
#include <math.h>
#include <stdint.h>

// ---------------- problem constants ----------------
#define C_DIM 768
#define NQ    13824      // 24^3 queries
#define NKV   1728       // 12^3 keys/values after SR
#define NH    8
#define HD    96
#define KCONV 6144       // 768 * 2*2*2
#define ALPHA_SCORE 0.35355339059327373f   // 1/sqrt(8)

// ---------------- scratch (device globals; no allocation allowed) ----------------
__device__ float g_q   [(size_t)NQ  * C_DIM];            // 42.5 MB
__device__ float g_col [(size_t)NKV * KCONV];            // 42.5 MB
__device__ float g_xr  [(size_t)NKV * C_DIM];            //  5.3 MB
__device__ float g_kv  [(size_t)NKV * 2 * C_DIM];        // 10.6 MB
__device__ float g_s   [(size_t)NH * NQ * NKV];          // 764 MB (all heads)
__device__ float g_attn[(size_t)NQ  * C_DIM];            // 42.5 MB

// ---------------- helpers ----------------
__device__ __forceinline__ float f2tf32(float x) {
    uint32_t u;
    asm("cvt.rna.tf32.f32 %0, %1;" : "=r"(u) : "f"(x));
    return __uint_as_float(u);
}

__device__ __forceinline__ void mma_tf32(float c[4], const uint32_t a[4], const uint32_t b[2]) {
    asm volatile(
        "mma.sync.aligned.m16n8k8.row.col.f32.tf32.tf32.f32 "
        "{%0,%1,%2,%3}, {%4,%5,%6,%7}, {%8,%9}, {%0,%1,%2,%3};"
        : "+f"(c[0]), "+f"(c[1]), "+f"(c[2]), "+f"(c[3])
        : "r"(a[0]), "r"(a[1]), "r"(a[2]), "r"(a[3]), "r"(b[0]), "r"(b[1]));
}

// ---------------- TF32 tensor-core GEMM ----------------
// C[M,N] = alpha * A[M,K] @ B + bias(col)
// B is [K,N] row-major, or [N,K] row-major if TRANSB (i.e. C = A @ B^T).
// Tile: BM=128, BN=128, BK=16, 256 threads (8 warps, warp grid 2x4, warp tile 64x32).
// Batched over blockIdx.z with element strides sA/sB/sC.
// Requirements: K % 16 == 0, N % 8 == 0, lda/ldb % 4 == 0, base ptrs 16B aligned.
template <bool TRANSB>
__global__ __launch_bounds__(256) void tgemm(
    const float* __restrict__ A, const float* __restrict__ B,
    float* __restrict__ C, const float* __restrict__ bias,
    float alpha, int M, int N, int K, int lda, int ldb, int ldc,
    long long sA, long long sB, long long sC)
{
    A += (long long)blockIdx.z * sA;
    B += (long long)blockIdx.z * sB;
    C += (long long)blockIdx.z * sC;

    __shared__ float As[2][16][132];   // [k][m], pad 4 -> conflict-free frag loads
    __shared__ float Bs[2][16][132];   // [k][n]

    const int tid  = threadIdx.x;
    const int lane = tid & 31, warp = tid >> 5;
    const int wm = warp >> 2;          // 0..1
    const int wn = warp & 3;           // 0..3
    const int quad = lane >> 2;        // 0..7
    const int qt   = lane & 3;         // 0..3
    const int m0 = blockIdx.y * 128;
    const int n0 = blockIdx.x * 128;

    float acc[4][4][4];
#pragma unroll
    for (int i = 0; i < 4; ++i)
#pragma unroll
        for (int j = 0; j < 4; ++j)
#pragma unroll
            for (int e = 0; e < 4; ++e) acc[i][j][e] = 0.f;

    // loader indices
    const int arow = tid >> 1;         // 0..127  (m for A, n for trans-B)
    const int ak   = (tid & 1) * 8;    // 0 or 8  (k)
    const int bk   = tid >> 4;         // 0..15   (k for non-trans B)
    const int bn   = (tid & 15) * 8;   // 0..120  (n)

    const int KT = K / 16;

    float4 ra0, ra1, rb0, rb1;
    const float4 z4 = make_float4(0.f, 0.f, 0.f, 0.f);

    auto load_tile = [&](int kt) {
        const int k0 = kt * 16;
        const int gm = m0 + arow;
        if (gm < M) {
            const float* p = A + (long long)gm * lda + k0 + ak;
            ra0 = *(const float4*)p;
            ra1 = *(const float4*)(p + 4);
        } else { ra0 = z4; ra1 = z4; }
        if (TRANSB) {
            const int gn = n0 + arow;
            if (gn < N) {
                const float* p = B + (long long)gn * ldb + k0 + ak;
                rb0 = *(const float4*)p;
                rb1 = *(const float4*)(p + 4);
            } else { rb0 = z4; rb1 = z4; }
        } else {
            const int gn = n0 + bn;
            if (gn < N) {   // N % 8 == 0 -> both float4s valid
                const float* p = B + (long long)(k0 + bk) * ldb + gn;
                rb0 = *(const float4*)p;
                rb1 = *(const float4*)(p + 4);
            } else { rb0 = z4; rb1 = z4; }
        }
    };

    auto store_tile = [&](int b) {
        As[b][ak + 0][arow] = f2tf32(ra0.x);
        As[b][ak + 1][arow] = f2tf32(ra0.y);
        As[b][ak + 2][arow] = f2tf32(ra0.z);
        As[b][ak + 3][arow] = f2tf32(ra0.w);
        As[b][ak + 4][arow] = f2tf32(ra1.x);
        As[b][ak + 5][arow] = f2tf32(ra1.y);
        As[b][ak + 6][arow] = f2tf32(ra1.z);
        As[b][ak + 7][arow] = f2tf32(ra1.w);
        if (TRANSB) {
            Bs[b][ak + 0][arow] = f2tf32(rb0.x);
            Bs[b][ak + 1][arow] = f2tf32(rb0.y);
            Bs[b][ak + 2][arow] = f2tf32(rb0.z);
            Bs[b][ak + 3][arow] = f2tf32(rb0.w);
            Bs[b][ak + 4][arow] = f2tf32(rb1.x);
            Bs[b][ak + 5][arow] = f2tf32(rb1.y);
            Bs[b][ak + 6][arow] = f2tf32(rb1.z);
            Bs[b][ak + 7][arow] = f2tf32(rb1.w);
        } else {
            float4 c0 = make_float4(f2tf32(rb0.x), f2tf32(rb0.y), f2tf32(rb0.z), f2tf32(rb0.w));
            float4 c1 = make_float4(f2tf32(rb1.x), f2tf32(rb1.y), f2tf32(rb1.z), f2tf32(rb1.w));
            *(float4*)&Bs[b][bk][bn]     = c0;
            *(float4*)&Bs[b][bk][bn + 4] = c1;
        }
    };

    load_tile(0);
    store_tile(0);
    __syncthreads();

    for (int kt = 0; kt < KT; ++kt) {
        const int cur = kt & 1;
        if (kt + 1 < KT) load_tile(kt + 1);

#pragma unroll
        for (int ks = 0; ks < 2; ++ks) {
            const int k8 = ks * 8;
            uint32_t av[4][4], bv[4][2];
#pragma unroll
            for (int mt = 0; mt < 4; ++mt) {
                const int row = wm * 64 + mt * 16 + quad;
                av[mt][0] = __float_as_uint(As[cur][k8 + qt    ][row]);
                av[mt][1] = __float_as_uint(As[cur][k8 + qt    ][row + 8]);
                av[mt][2] = __float_as_uint(As[cur][k8 + qt + 4][row]);
                av[mt][3] = __float_as_uint(As[cur][k8 + qt + 4][row + 8]);
            }
#pragma unroll
            for (int nt = 0; nt < 4; ++nt) {
                const int col = wn * 32 + nt * 8 + quad;
                bv[nt][0] = __float_as_uint(Bs[cur][k8 + qt    ][col]);
                bv[nt][1] = __float_as_uint(Bs[cur][k8 + qt + 4][col]);
            }
#pragma unroll
            for (int mt = 0; mt < 4; ++mt)
#pragma unroll
                for (int nt = 0; nt < 4; ++nt)
                    mma_tf32(acc[mt][nt], av[mt], bv[nt]);
        }

        if (kt + 1 < KT) store_tile((kt + 1) & 1);
        __syncthreads();
    }

    // epilogue
#pragma unroll
    for (int mt = 0; mt < 4; ++mt) {
        const int r = m0 + wm * 64 + mt * 16 + quad;
#pragma unroll
        for (int nt = 0; nt < 4; ++nt) {
            const int c = n0 + wn * 32 + nt * 8 + 2 * qt;
            float v0 = acc[mt][nt][0] * alpha;
            float v1 = acc[mt][nt][1] * alpha;
            float v2 = acc[mt][nt][2] * alpha;
            float v3 = acc[mt][nt][3] * alpha;
            if (bias) {
                const float b0 = bias[c], b1 = bias[c + 1];
                v0 += b0; v1 += b1; v2 += b0; v3 += b1;
            }
            if (r < M && c < N) {
                C[(long long)r * ldc + c]     = v0;
                C[(long long)r * ldc + c + 1] = v1;
            }
            if (r + 8 < M && c < N) {
                C[(long long)(r + 8) * ldc + c]     = v2;
                C[(long long)(r + 8) * ldc + c + 1] = v3;
            }
        }
    }
}

// ---------------- im2col for SR conv (kernel=stride=2) ----------------
__global__ void im2col_kernel(const float* __restrict__ x, float* __restrict__ col)
{
    const long long idx = (long long)blockIdx.x * blockDim.x + threadIdx.x;
    if (idx >= (long long)NKV * KCONV) return;
    const int p = (int)(idx / KCONV);
    const int r = (int)(idx - (long long)p * KCONV);
    const int ci = r >> 3;
    const int corner = r & 7;
    const int dz = corner >> 2, dy = (corner >> 1) & 1, dx = corner & 1;
    const int pz = p / 144;
    const int rem = p - pz * 144;
    const int py = rem / 12;
    const int px = rem - py * 12;
    const int pos = ((2 * pz + dz) * 24 + (2 * py + dy)) * 24 + (2 * px + dx);
    col[idx] = x[(size_t)pos * C_DIM + ci];
}

// ---------------- row LayerNorm over C, in-place ----------------
__global__ void ln_kernel(float* __restrict__ X,
                          const float* __restrict__ g, const float* __restrict__ b)
{
    const int r = blockIdx.x;
    float* row = X + (size_t)r * C_DIM;
    __shared__ float s1[256], s2[256];
    const int t = threadIdx.x;
    float sum = 0.f, sq = 0.f;
    for (int i = t; i < C_DIM; i += 256) { float v = row[i]; sum += v; sq += v * v; }
    s1[t] = sum; s2[t] = sq;
    __syncthreads();
    for (int st = 128; st > 0; st >>= 1) {
        if (t < st) { s1[t] += s1[t + st]; s2[t] += s2[t + st]; }
        __syncthreads();
    }
    const float mu  = s1[0] * (1.f / C_DIM);
    const float var = s2[0] * (1.f / C_DIM) - mu * mu;
    const float inv = rsqrtf(var + 1e-5f);
    for (int i = t; i < C_DIM; i += 256)
        row[i] = (row[i] - mu) * inv * g[i] + b[i];
}

// ---------------- softmax over NKV, row cached in smem (1 read + 1 write) ----------------
__global__ void softmax_kernel(float* __restrict__ S)
{
    const size_t row_idx = (size_t)blockIdx.y * NQ + blockIdx.x;
    float* row = S + row_idx * NKV;
    __shared__ float buf[NKV];
    __shared__ float red[256];
    const int t = threadIdx.x;

    float m = -1e30f;
    for (int i = t; i < NKV; i += 256) {
        const float v = row[i];
        buf[i] = v;
        m = fmaxf(m, v);
    }
    red[t] = m;
    __syncthreads();
    for (int st = 128; st > 0; st >>= 1) {
        if (t < st) red[t] = fmaxf(red[t], red[t + st]);
        __syncthreads();
    }
    m = red[0];
    __syncthreads();

    float sum = 0.f;
    for (int i = t; i < NKV; i += 256) {
        const float e = __expf(buf[i] - m);
        buf[i] = e;
        sum += e;
    }
    red[t] = sum;
    __syncthreads();
    for (int st = 128; st > 0; st >>= 1) {
        if (t < st) red[t] += red[t + st];
        __syncthreads();
    }
    const float inv = 1.f / red[0];
    for (int i = t; i < NKV; i += 256) row[i] = buf[i] * inv;
}

// ---------------- launch ----------------
extern "C" void kernel_launch(void* const* d_in, const int* in_sizes, int n_in,
                              void* d_out, int out_size)
{
    const float* x      = (const float*)d_in[0];
    const float* wq     = (const float*)d_in[1];
    const float* wkv    = (const float*)d_in[2];
    const float* sr_w   = (const float*)d_in[3];
    const float* sr_b   = (const float*)d_in[4];
    const float* ln_g   = (const float*)d_in[5];
    const float* ln_b   = (const float*)d_in[6];
    const float* proj_w = (const float*)d_in[7];
    const float* proj_b = (const float*)d_in[8];
    float* out = (float*)d_out;

    float *q, *col, *xr, *kv, *s, *attn;
    cudaGetSymbolAddress((void**)&q,    g_q);
    cudaGetSymbolAddress((void**)&col,  g_col);
    cudaGetSymbolAddress((void**)&xr,   g_xr);
    cudaGetSymbolAddress((void**)&kv,   g_kv);
    cudaGetSymbolAddress((void**)&s,    g_s);
    cudaGetSymbolAddress((void**)&attn, g_attn);

    const dim3 blk(256);

    // 1) Q = x @ wq                       [13824,768] x [768,768]
    tgemm<false><<<dim3(6, 108, 1), blk>>>(
        x, wq, q, nullptr, 1.f, NQ, C_DIM, C_DIM, C_DIM, C_DIM, C_DIM, 0, 0, 0);

    // 2) im2col
    {
        long long tot = (long long)NKV * KCONV;
        im2col_kernel<<<(unsigned)((tot + 255) / 256), blk>>>(x, col);
    }

    // 3) conv-as-GEMM: xr = col @ sr_w^T + sr_b    [1728,6144] x [768,6144]^T
    tgemm<true><<<dim3(6, 14, 1), blk>>>(
        col, sr_w, xr, sr_b, 1.f, NKV, C_DIM, KCONV, KCONV, KCONV, C_DIM, 0, 0, 0);

    // 4) LayerNorm rows of xr
    ln_kernel<<<NKV, blk>>>(xr, ln_g, ln_b);

    // 5) KV = xr @ wkv                    [1728,768] x [768,1536]
    tgemm<false><<<dim3(12, 14, 1), blk>>>(
        xr, wkv, kv, nullptr, 1.f, NKV, 2 * C_DIM, C_DIM, C_DIM, 2 * C_DIM, 2 * C_DIM,
        0, 0, 0);

    // 6a) scores (all heads): s[h] = (q_h @ k_h^T) / sqrt(8)
    tgemm<true><<<dim3(14, 108, NH), blk>>>(
        q, kv, s, nullptr, ALPHA_SCORE,
        NQ, NKV, HD, C_DIM, 2 * C_DIM, NKV,
        (long long)HD, (long long)HD, (long long)NQ * NKV);

    // 6b) softmax rows (all heads)
    softmax_kernel<<<dim3(NQ, NH), blk>>>(s);

    // 6c) attn[:, h*96:...] = probs_h @ v_h
    tgemm<false><<<dim3(1, 108, NH), blk>>>(
        s, kv + C_DIM, attn, nullptr, 1.f,
        NQ, HD, NKV, NKV, 2 * C_DIM, C_DIM,
        (long long)NQ * NKV, (long long)HD, (long long)HD);

    // 7) out = attn @ proj_w + proj_b
    tgemm<false><<<dim3(6, 108, 1), blk>>>(
        attn, proj_w, out, proj_b, 1.f, NQ, C_DIM, C_DIM, C_DIM, C_DIM, C_DIM, 0, 0, 0);
}

// round 5
// speedup vs baseline: 2.7132x; 1.0921x over previous
#include <cuda_runtime.h>
#include <math.h>
#include <stdint.h>

// ---------------- problem constants ----------------
#define C_DIM 768
#define NQ    13824      // 24^3 queries
#define NKV   1728       // 12^3 keys/values after SR
#define NH    8
#define HD    96
#define KCONV 6144       // 768 * 2*2*2
#define ALPHA_SCORE 0.35355339059327373f   // 1/sqrt(8)

// ---------------- scratch (device globals; no allocation allowed) ----------------
__device__ float g_q   [(size_t)NQ  * C_DIM];            // 42.5 MB
__device__ float g_col [(size_t)NKV * KCONV];            // 42.5 MB
__device__ float g_xr2 [2 * (size_t)NKV * C_DIM];        // 10.6 MB (split-K partials)
__device__ float g_xr  [(size_t)NKV * C_DIM];            //  5.3 MB
__device__ float g_kv  [(size_t)NKV * 2 * C_DIM];        // 10.6 MB (tf32-rounded)
__device__ float g_attn[(size_t)NQ  * C_DIM];            // 42.5 MB

// ---------------- helpers ----------------
__device__ __forceinline__ float f2tf32(float x) {
    uint32_t u;
    asm("cvt.rna.tf32.f32 %0, %1;" : "=r"(u) : "f"(x));
    return __uint_as_float(u);
}

__device__ __forceinline__ void mma_tf32(float c[4], const uint32_t a[4], const uint32_t b[2]) {
    asm volatile(
        "mma.sync.aligned.m16n8k8.row.col.f32.tf32.tf32.f32 "
        "{%0,%1,%2,%3}, {%4,%5,%6,%7}, {%8,%9}, {%0,%1,%2,%3};"
        : "+f"(c[0]), "+f"(c[1]), "+f"(c[2]), "+f"(c[3])
        : "r"(a[0]), "r"(a[1]), "r"(a[2]), "r"(a[3]), "r"(b[0]), "r"(b[1]));
}

__device__ __forceinline__ void mma_tf32s(float c[4], const uint32_t a[4],
                                          uint32_t b0, uint32_t b1) {
    asm volatile(
        "mma.sync.aligned.m16n8k8.row.col.f32.tf32.tf32.f32 "
        "{%0,%1,%2,%3}, {%4,%5,%6,%7}, {%8,%9}, {%0,%1,%2,%3};"
        : "+f"(c[0]), "+f"(c[1]), "+f"(c[2]), "+f"(c[3])
        : "r"(a[0]), "r"(a[1]), "r"(a[2]), "r"(a[3]), "r"(b0), "r"(b1));
}

__device__ __forceinline__ void cp16(uint32_t saddr, const void* g) {
    asm volatile("cp.async.cg.shared.global [%0], [%1], 16;" :: "r"(saddr), "l"(g));
}

// ---------------- TF32 tensor-core GEMM (validated round-4 kernel + tf32out flag) ----------------
template <bool TRANSB>
__global__ __launch_bounds__(256) void tgemm(
    const float* __restrict__ A, const float* __restrict__ B,
    float* __restrict__ C, const float* __restrict__ bias,
    float alpha, int M, int N, int K, int lda, int ldb, int ldc,
    long long sA, long long sB, long long sC, int tf32out)
{
    A += (long long)blockIdx.z * sA;
    B += (long long)blockIdx.z * sB;
    C += (long long)blockIdx.z * sC;

    __shared__ float As[2][16][132];
    __shared__ float Bs[2][16][132];

    const int tid  = threadIdx.x;
    const int lane = tid & 31, warp = tid >> 5;
    const int wm = warp >> 2;
    const int wn = warp & 3;
    const int quad = lane >> 2;
    const int qt   = lane & 3;
    const int m0 = blockIdx.y * 128;
    const int n0 = blockIdx.x * 128;

    float acc[4][4][4];
#pragma unroll
    for (int i = 0; i < 4; ++i)
#pragma unroll
        for (int j = 0; j < 4; ++j)
#pragma unroll
            for (int e = 0; e < 4; ++e) acc[i][j][e] = 0.f;

    const int arow = tid >> 1;
    const int ak   = (tid & 1) * 8;
    const int bk   = tid >> 4;
    const int bn   = (tid & 15) * 8;

    const int KT = K / 16;

    float4 ra0, ra1, rb0, rb1;
    const float4 z4 = make_float4(0.f, 0.f, 0.f, 0.f);

    auto load_tile = [&](int kt) {
        const int k0 = kt * 16;
        const int gm = m0 + arow;
        if (gm < M) {
            const float* p = A + (long long)gm * lda + k0 + ak;
            ra0 = *(const float4*)p;
            ra1 = *(const float4*)(p + 4);
        } else { ra0 = z4; ra1 = z4; }
        if (TRANSB) {
            const int gn = n0 + arow;
            if (gn < N) {
                const float* p = B + (long long)gn * ldb + k0 + ak;
                rb0 = *(const float4*)p;
                rb1 = *(const float4*)(p + 4);
            } else { rb0 = z4; rb1 = z4; }
        } else {
            const int gn = n0 + bn;
            if (gn < N) {
                const float* p = B + (long long)(k0 + bk) * ldb + gn;
                rb0 = *(const float4*)p;
                rb1 = *(const float4*)(p + 4);
            } else { rb0 = z4; rb1 = z4; }
        }
    };

    auto store_tile = [&](int b) {
        As[b][ak + 0][arow] = f2tf32(ra0.x);
        As[b][ak + 1][arow] = f2tf32(ra0.y);
        As[b][ak + 2][arow] = f2tf32(ra0.z);
        As[b][ak + 3][arow] = f2tf32(ra0.w);
        As[b][ak + 4][arow] = f2tf32(ra1.x);
        As[b][ak + 5][arow] = f2tf32(ra1.y);
        As[b][ak + 6][arow] = f2tf32(ra1.z);
        As[b][ak + 7][arow] = f2tf32(ra1.w);
        if (TRANSB) {
            Bs[b][ak + 0][arow] = f2tf32(rb0.x);
            Bs[b][ak + 1][arow] = f2tf32(rb0.y);
            Bs[b][ak + 2][arow] = f2tf32(rb0.z);
            Bs[b][ak + 3][arow] = f2tf32(rb0.w);
            Bs[b][ak + 4][arow] = f2tf32(rb1.x);
            Bs[b][ak + 5][arow] = f2tf32(rb1.y);
            Bs[b][ak + 6][arow] = f2tf32(rb1.z);
            Bs[b][ak + 7][arow] = f2tf32(rb1.w);
        } else {
            float4 c0 = make_float4(f2tf32(rb0.x), f2tf32(rb0.y), f2tf32(rb0.z), f2tf32(rb0.w));
            float4 c1 = make_float4(f2tf32(rb1.x), f2tf32(rb1.y), f2tf32(rb1.z), f2tf32(rb1.w));
            *(float4*)&Bs[b][bk][bn]     = c0;
            *(float4*)&Bs[b][bk][bn + 4] = c1;
        }
    };

    load_tile(0);
    store_tile(0);
    __syncthreads();

    for (int kt = 0; kt < KT; ++kt) {
        const int cur = kt & 1;
        if (kt + 1 < KT) load_tile(kt + 1);

#pragma unroll
        for (int ks = 0; ks < 2; ++ks) {
            const int k8 = ks * 8;
            uint32_t av[4][4], bv[4][2];
#pragma unroll
            for (int mt = 0; mt < 4; ++mt) {
                const int row = wm * 64 + mt * 16 + quad;
                av[mt][0] = __float_as_uint(As[cur][k8 + qt    ][row]);
                av[mt][1] = __float_as_uint(As[cur][k8 + qt    ][row + 8]);
                av[mt][2] = __float_as_uint(As[cur][k8 + qt + 4][row]);
                av[mt][3] = __float_as_uint(As[cur][k8 + qt + 4][row + 8]);
            }
#pragma unroll
            for (int nt = 0; nt < 4; ++nt) {
                const int col = wn * 32 + nt * 8 + quad;
                bv[nt][0] = __float_as_uint(Bs[cur][k8 + qt    ][col]);
                bv[nt][1] = __float_as_uint(Bs[cur][k8 + qt + 4][col]);
            }
#pragma unroll
            for (int mt = 0; mt < 4; ++mt)
#pragma unroll
                for (int nt = 0; nt < 4; ++nt)
                    mma_tf32(acc[mt][nt], av[mt], bv[nt]);
        }

        if (kt + 1 < KT) store_tile((kt + 1) & 1);
        __syncthreads();
    }

#pragma unroll
    for (int mt = 0; mt < 4; ++mt) {
        const int r = m0 + wm * 64 + mt * 16 + quad;
#pragma unroll
        for (int nt = 0; nt < 4; ++nt) {
            const int c = n0 + wn * 32 + nt * 8 + 2 * qt;
            float v0 = acc[mt][nt][0] * alpha;
            float v1 = acc[mt][nt][1] * alpha;
            float v2 = acc[mt][nt][2] * alpha;
            float v3 = acc[mt][nt][3] * alpha;
            if (bias) {
                const float b0 = bias[c], b1 = bias[c + 1];
                v0 += b0; v1 += b1; v2 += b0; v3 += b1;
            }
            if (tf32out) {
                v0 = f2tf32(v0); v1 = f2tf32(v1); v2 = f2tf32(v2); v3 = f2tf32(v3);
            }
            if (r < M && c < N) {
                C[(long long)r * ldc + c]     = v0;
                C[(long long)r * ldc + c + 1] = v1;
            }
            if (r + 8 < M && c < N) {
                C[(long long)(r + 8) * ldc + c]     = v2;
                C[(long long)(r + 8) * ldc + c + 1] = v3;
            }
        }
    }
}

// ---------------- fused flash attention ----------------
// grid (108, 8): 128 queries x 1 head per CTA. 256 threads, 8 warps x 16 q-rows.
// KV tiles of 96 (18 exact tiles), double-buffered cp.async.
// smem floats: K0@0(96x100) K1@9600 V0@19200(96x104) V1@29184; total 39168 fl = 156672 B.
#define FK_STR 100
#define FV_STR 104
#define FSMEM_BYTES ((2 * 96 * FK_STR + 2 * 96 * FV_STR) * 4)

__global__ __launch_bounds__(256) void flash_kernel(
    const float* __restrict__ Q, const float* __restrict__ KV, float* __restrict__ Out)
{
    extern __shared__ float sm[];
    const int h  = blockIdx.y;
    const int q0 = blockIdx.x * 128;
    const int tid = threadIdx.x;
    const int lane = tid & 31, warp = tid >> 5;
    const int quad = lane >> 2, t = lane & 3;

    // ---- stage Q tile (scaled by alpha), grab A-fragments ----
    for (int i = tid; i < 128 * 24; i += 256) {
        const int r = i / 24, c = (i % 24) * 4;
        float4 v = *(const float4*)(Q + (size_t)(q0 + r) * C_DIM + h * HD + c);
        float* d = sm + r * FK_STR + c;
        d[0] = v.x * ALPHA_SCORE; d[1] = v.y * ALPHA_SCORE;
        d[2] = v.z * ALPHA_SCORE; d[3] = v.w * ALPHA_SCORE;
    }
    __syncthreads();

    uint32_t aQ[12][4];
    const int row = warp * 16 + quad;
#pragma unroll
    for (int kc = 0; kc < 12; ++kc) {
        aQ[kc][0] = __float_as_uint(f2tf32(sm[row * FK_STR + kc * 8 + t]));
        aQ[kc][1] = __float_as_uint(f2tf32(sm[(row + 8) * FK_STR + kc * 8 + t]));
        aQ[kc][2] = __float_as_uint(f2tf32(sm[row * FK_STR + kc * 8 + t + 4]));
        aQ[kc][3] = __float_as_uint(f2tf32(sm[(row + 8) * FK_STR + kc * 8 + t + 4]));
    }
    __syncthreads();   // Q staging dead; K/V buffers may now be written

    const uint32_t smem_u32 = (uint32_t)__cvta_generic_to_shared(sm);

    auto load_tile = [&](int kvt, int buf) {
        const float* gbase = KV + (size_t)(kvt * 96) * (2 * C_DIM) + h * HD;
        const uint32_t sk = smem_u32 + (buf ? 9600u * 4u : 0u);
        const uint32_t sv = smem_u32 + 19200u * 4u + (buf ? 9984u * 4u : 0u);
        for (int i = tid; i < 96 * 24; i += 256) {
            const int j = i / 24, c = (i % 24) * 4;
            const float* g = gbase + (size_t)j * (2 * C_DIM) + c;
            cp16(sk + (uint32_t)(j * FK_STR + c) * 4u, g);
            cp16(sv + (uint32_t)(j * FV_STR + c) * 4u, g + C_DIM);
        }
        asm volatile("cp.async.commit_group;" ::: "memory");
    };

    float Oa[12][4];
#pragma unroll
    for (int nf = 0; nf < 12; ++nf) { Oa[nf][0] = Oa[nf][1] = Oa[nf][2] = Oa[nf][3] = 0.f; }
    float m0 = -1e30f, m1 = -1e30f, l0 = 0.f, l1 = 0.f;

    load_tile(0, 0);

    for (int kvt = 0; kvt < 18; ++kvt) {
        const int cur = kvt & 1;
        asm volatile("cp.async.wait_group 0;" ::: "memory");
        __syncthreads();
        if (kvt + 1 < 18) load_tile(kvt + 1, cur ^ 1);

        const float* Kb = sm + (cur ? 9600 : 0);
        const float* Vb = sm + 19200 + (cur ? 9984 : 0);

        // ---- S = Qa @ K^T (144 mma) ----
        float s[12][4];
#pragma unroll
        for (int nf = 0; nf < 12; ++nf) { s[nf][0] = s[nf][1] = s[nf][2] = s[nf][3] = 0.f; }
#pragma unroll
        for (int kc = 0; kc < 12; ++kc) {
            const float* kp = Kb + kc * 8 + t;
#pragma unroll
            for (int nf = 0; nf < 12; ++nf) {
                const uint32_t b0 = __float_as_uint(kp[(nf * 8 + quad) * FK_STR]);
                const uint32_t b1 = __float_as_uint(kp[(nf * 8 + quad) * FK_STR + 4]);
                mma_tf32s(s[nf], aQ[kc], b0, b1);
            }
        }

        // ---- online softmax ----
        float mx0 = -1e30f, mx1 = -1e30f;
#pragma unroll
        for (int nf = 0; nf < 12; ++nf) {
            mx0 = fmaxf(mx0, fmaxf(s[nf][0], s[nf][1]));
            mx1 = fmaxf(mx1, fmaxf(s[nf][2], s[nf][3]));
        }
        mx0 = fmaxf(mx0, __shfl_xor_sync(0xffffffffu, mx0, 1));
        mx0 = fmaxf(mx0, __shfl_xor_sync(0xffffffffu, mx0, 2));
        mx1 = fmaxf(mx1, __shfl_xor_sync(0xffffffffu, mx1, 1));
        mx1 = fmaxf(mx1, __shfl_xor_sync(0xffffffffu, mx1, 2));

        const float mn0 = fmaxf(m0, mx0), mn1 = fmaxf(m1, mx1);
        const float cr0 = __expf(m0 - mn0), cr1 = __expf(m1 - mn1);
        m0 = mn0; m1 = mn1;

        float sum0 = 0.f, sum1 = 0.f;
#pragma unroll
        for (int nf = 0; nf < 12; ++nf) {
            float p0 = f2tf32(__expf(s[nf][0] - mn0));
            float p1 = f2tf32(__expf(s[nf][1] - mn0));
            float p2 = f2tf32(__expf(s[nf][2] - mn1));
            float p3 = f2tf32(__expf(s[nf][3] - mn1));
            s[nf][0] = p0; s[nf][1] = p1; s[nf][2] = p2; s[nf][3] = p3;
            sum0 += p0 + p1; sum1 += p2 + p3;
        }
        sum0 += __shfl_xor_sync(0xffffffffu, sum0, 1);
        sum0 += __shfl_xor_sync(0xffffffffu, sum0, 2);
        sum1 += __shfl_xor_sync(0xffffffffu, sum1, 1);
        sum1 += __shfl_xor_sync(0xffffffffu, sum1, 2);
        l0 = l0 * cr0 + sum0;
        l1 = l1 * cr1 + sum1;

#pragma unroll
        for (int nf = 0; nf < 12; ++nf) {
            Oa[nf][0] *= cr0; Oa[nf][1] *= cr0;
            Oa[nf][2] *= cr1; Oa[nf][3] *= cr1;
        }

        // ---- O += P @ V (144 mma, A-frags built by intra-quad shuffles) ----
        const int src1 = (lane & ~3) | (t >> 1);
        const int src2 = src1 + 2;
        const bool odd = (t & 1);
#pragma unroll
        for (int kc = 0; kc < 12; ++kc) {
            const float p0 = s[kc][0], p1 = s[kc][1], p2 = s[kc][2], p3 = s[kc][3];
            const float q00 = __shfl_sync(0xffffffffu, p0, src1);
            const float q01 = __shfl_sync(0xffffffffu, p1, src1);
            const float q10 = __shfl_sync(0xffffffffu, p2, src1);
            const float q11 = __shfl_sync(0xffffffffu, p3, src1);
            const float r00 = __shfl_sync(0xffffffffu, p0, src2);
            const float r01 = __shfl_sync(0xffffffffu, p1, src2);
            const float r10 = __shfl_sync(0xffffffffu, p2, src2);
            const float r11 = __shfl_sync(0xffffffffu, p3, src2);
            uint32_t aP[4];
            aP[0] = __float_as_uint(odd ? q01 : q00);
            aP[1] = __float_as_uint(odd ? q11 : q10);
            aP[2] = __float_as_uint(odd ? r01 : r00);
            aP[3] = __float_as_uint(odd ? r11 : r10);

            const float* vp = Vb + (kc * 8 + t) * FV_STR + quad;
#pragma unroll
            for (int nf = 0; nf < 12; ++nf) {
                const uint32_t b0 = __float_as_uint(vp[nf * 8]);
                const uint32_t b1 = __float_as_uint(vp[nf * 8 + 4 * FV_STR]);
                mma_tf32s(Oa[nf], aP, b0, b1);
            }
        }
        __syncthreads();   // done reading this buffer before it is refilled
    }

    // ---- normalize + write ----
    const float inv0 = 1.f / l0, inv1 = 1.f / l1;
    float* op  = Out + (size_t)(q0 + row) * C_DIM + h * HD + 2 * t;
    float* op8 = op + 8 * C_DIM;
#pragma unroll
    for (int nf = 0; nf < 12; ++nf) {
        *(float2*)(op  + nf * 8) = make_float2(Oa[nf][0] * inv0, Oa[nf][1] * inv0);
        *(float2*)(op8 + nf * 8) = make_float2(Oa[nf][2] * inv1, Oa[nf][3] * inv1);
    }
}

// ---------------- im2col for SR conv (kernel=stride=2) ----------------
__global__ void im2col_kernel(const float* __restrict__ x, float* __restrict__ col)
{
    const long long idx = (long long)blockIdx.x * blockDim.x + threadIdx.x;
    if (idx >= (long long)NKV * KCONV) return;
    const int p = (int)(idx / KCONV);
    const int r = (int)(idx - (long long)p * KCONV);
    const int ci = r >> 3;
    const int corner = r & 7;
    const int dz = corner >> 2, dy = (corner >> 1) & 1, dx = corner & 1;
    const int pz = p / 144;
    const int rem = p - pz * 144;
    const int py = rem / 12;
    const int px = rem - py * 12;
    const int pos = ((2 * pz + dz) * 24 + (2 * py + dy)) * 24 + (2 * px + dx);
    col[idx] = x[(size_t)pos * C_DIM + ci];
}

// ---------------- fused split-K sum + conv bias + LayerNorm ----------------
__global__ void ln2_kernel(const float* __restrict__ X0, const float* __restrict__ X1,
                           const float* __restrict__ cb,
                           const float* __restrict__ g, const float* __restrict__ b,
                           float* __restrict__ Y)
{
    const int r = blockIdx.x;
    const float* r0 = X0 + (size_t)r * C_DIM;
    const float* r1 = X1 + (size_t)r * C_DIM;
    float* out = Y + (size_t)r * C_DIM;
    __shared__ float buf[C_DIM];
    __shared__ float s1[256], s2[256];
    const int t = threadIdx.x;
    float sum = 0.f, sq = 0.f;
    for (int i = t; i < C_DIM; i += 256) {
        const float v = r0[i] + r1[i] + cb[i];
        buf[i] = v;
        sum += v; sq += v * v;
    }
    s1[t] = sum; s2[t] = sq;
    __syncthreads();
    for (int st = 128; st > 0; st >>= 1) {
        if (t < st) { s1[t] += s1[t + st]; s2[t] += s2[t + st]; }
        __syncthreads();
    }
    const float mu  = s1[0] * (1.f / C_DIM);
    const float var = s2[0] * (1.f / C_DIM) - mu * mu;
    const float inv = rsqrtf(var + 1e-5f);
    for (int i = t; i < C_DIM; i += 256)
        out[i] = (buf[i] - mu) * inv * g[i] + b[i];
}

// ---------------- launch ----------------
extern "C" void kernel_launch(void* const* d_in, const int* in_sizes, int n_in,
                              void* d_out, int out_size)
{
    const float* x      = (const float*)d_in[0];
    const float* wq     = (const float*)d_in[1];
    const float* wkv    = (const float*)d_in[2];
    const float* sr_w   = (const float*)d_in[3];
    const float* sr_b   = (const float*)d_in[4];
    const float* ln_g   = (const float*)d_in[5];
    const float* ln_b   = (const float*)d_in[6];
    const float* proj_w = (const float*)d_in[7];
    const float* proj_b = (const float*)d_in[8];
    float* out = (float*)d_out;

    float *q, *col, *xr2, *xr, *kv, *attn;
    cudaGetSymbolAddress((void**)&q,    g_q);
    cudaGetSymbolAddress((void**)&col,  g_col);
    cudaGetSymbolAddress((void**)&xr2,  g_xr2);
    cudaGetSymbolAddress((void**)&xr,   g_xr);
    cudaGetSymbolAddress((void**)&kv,   g_kv);
    cudaGetSymbolAddress((void**)&attn, g_attn);

    static int smem_set = 0;
    if (!smem_set) {
        cudaFuncSetAttribute(flash_kernel,
                             cudaFuncAttributeMaxDynamicSharedMemorySize, FSMEM_BYTES);
        smem_set = 1;
    }

    const dim3 blk(256);

    // 1) Q = x @ wq
    tgemm<false><<<dim3(6, 108, 1), blk>>>(
        x, wq, q, nullptr, 1.f, NQ, C_DIM, C_DIM, C_DIM, C_DIM, C_DIM, 0, 0, 0, 0);

    // 2) im2col
    {
        long long tot = (long long)NKV * KCONV;
        im2col_kernel<<<(unsigned)((tot + 255) / 256), blk>>>(x, col);
    }

    // 3) conv-as-GEMM, split-K x2: xr2[z] = col[:, z*3072:] @ sr_w[:, z*3072:]^T
    tgemm<true><<<dim3(6, 14, 2), blk>>>(
        col, sr_w, xr2, nullptr, 1.f, NKV, C_DIM, KCONV / 2, KCONV, KCONV, C_DIM,
        (long long)(KCONV / 2), (long long)(KCONV / 2), (long long)NKV * C_DIM, 0);

    // 4) sum partials + conv bias + LayerNorm
    ln2_kernel<<<NKV, blk>>>(xr2, xr2 + (size_t)NKV * C_DIM, sr_b, ln_g, ln_b, xr);

    // 5) KV = xr @ wkv  (output rounded to tf32 for the flash kernel)
    tgemm<false><<<dim3(12, 14, 1), blk>>>(
        xr, wkv, kv, nullptr, 1.f, NKV, 2 * C_DIM, C_DIM, C_DIM, 2 * C_DIM, 2 * C_DIM,
        0, 0, 0, 1);

    // 6) fused attention (all heads)
    flash_kernel<<<dim3(NQ / 128, NH), blk, FSMEM_BYTES>>>(q, kv, attn);

    // 7) out = attn @ proj_w + proj_b
    tgemm<false><<<dim3(6, 108, 1), blk>>>(
        attn, proj_w, out, proj_b, 1.f, NQ, C_DIM, C_DIM, C_DIM, C_DIM, C_DIM, 0, 0, 0, 0);
}

// round 8
// speedup vs baseline: 9.7263x; 3.5848x over previous
#include <cuda_runtime.h>
#include <cuda_fp16.h>
#include <math.h>
#include <stdint.h>

// ---------------- problem constants ----------------
#define C_DIM 768
#define NQ    13824      // 24^3 queries
#define NKV   1728       // 12^3 keys/values after SR
#define NH    8
#define HD    96
#define KCONV 6144       // 768 * 2*2*2
#define ALPHA_SCORE 0.35355339059327373f   // 1/sqrt(8)

// ---------------- scratch (device globals; no allocation allowed) ----------------
__device__ __half g_x16  [(size_t)NQ * C_DIM];           // x fp16
__device__ __half g_wqt  [(size_t)C_DIM * C_DIM];        // wq^T fp16
__device__ __half g_wkvt [(size_t)2 * C_DIM * C_DIM];    // wkv^T fp16
__device__ __half g_pjt  [(size_t)C_DIM * C_DIM];        // proj^T fp16
__device__ __half g_srw  [(size_t)C_DIM * KCONV];        // sr_w fp16 (already [O][I*8])
__device__ __half g_col16[(size_t)NKV * KCONV];          // im2col fp16
__device__ __half g_q16  [(size_t)NQ * C_DIM];           // Q fp16 (pre-scaled by 1/sqrt(8))
__device__ float  g_xr2  [2 * (size_t)NKV * C_DIM];      // conv split-K fp32 partials
__device__ __half g_xr16 [(size_t)NKV * C_DIM];          // LN output fp16
__device__ __half g_kv16 [(size_t)NKV * 2 * C_DIM];      // [NKV][1536]: K | V
__device__ __half g_vt16 [(size_t)C_DIM * NKV];          // V^T: [c=h*96+d][NKV]
__device__ __half g_at16 [(size_t)NQ * C_DIM];           // attention output fp16

// ---------------- helpers ----------------
__device__ __forceinline__ void cp16(uint32_t saddr, const void* g) {
    asm volatile("cp.async.cg.shared.global [%0], [%1], 16;" :: "r"(saddr), "l"(g));
}
__device__ __forceinline__ void mma16(float c[4],
                                      uint32_t a0, uint32_t a1, uint32_t a2, uint32_t a3,
                                      uint32_t b0, uint32_t b1) {
    asm volatile(
        "mma.sync.aligned.m16n8k16.row.col.f32.f16.f16.f32 "
        "{%0,%1,%2,%3}, {%4,%5,%6,%7}, {%8,%9}, {%0,%1,%2,%3};"
        : "+f"(c[0]), "+f"(c[1]), "+f"(c[2]), "+f"(c[3])
        : "r"(a0), "r"(a1), "r"(a2), "r"(a3), "r"(b0), "r"(b1));
}
__device__ __forceinline__ uint32_t pack2(float x, float y) {
    __half2 h = __floats2half2_rn(x, y);
    return *reinterpret_cast<uint32_t*>(&h);
}
__device__ __forceinline__ float hrnd(float x) {       // round-trip through fp16
    return __half2float(__float2half_rn(x));
}
__device__ __forceinline__ uint32_t lds32(const __half* p) {
    return *reinterpret_cast<const uint32_t*>(p);
}

// ---------------- fp16 tensor-core GEMM ----------------
// C[M,N] = alpha * A[M,K] @ B[N,K]^T (+bias).  A,B fp16 row-major (k contiguous).
// Tile 128x128, BK=32, 256 threads (8 warps 2x4, warp tile 64x32), cp.async dbl-buffer.
// Requirements: N % 128 == 0, K % 32 == 0, lda/ldb % 8 == 0. M clamped.
// smem halves: A0@0(128x40) B0@5120 A1@10240 B1@15360  => 40960 bytes static.
template <bool OUT16>
__global__ __launch_bounds__(256) void tgemm16(
    const __half* __restrict__ A, const __half* __restrict__ B,
    void* __restrict__ Cv, const float* __restrict__ bias,
    float alpha, int M, int N, int K, int lda, int ldb, int ldc,
    long long zA, long long zB, long long zC)
{
    __shared__ __align__(16) __half ts[20480];
    const uint32_t smem_u32 = (uint32_t)__cvta_generic_to_shared(ts);

    A += (long long)blockIdx.z * zA;
    B += (long long)blockIdx.z * zB;

    const int tid = threadIdx.x;
    const int lane = tid & 31, warp = tid >> 5;
    const int wm = warp >> 2, wn = warp & 3;
    const int quad = lane >> 2, t = lane & 3;
    const int m0 = blockIdx.y * 128;
    const int n0 = blockIdx.x * 128;

    float acc[4][4][4];
#pragma unroll
    for (int i = 0; i < 4; ++i)
#pragma unroll
        for (int j = 0; j < 4; ++j)
#pragma unroll
            for (int e = 0; e < 4; ++e) acc[i][j][e] = 0.f;

    const int KT = K / 32;

    auto load_tile = [&](int kt, int buf) {
        const int k0 = kt * 32;
        const uint32_t sA = smem_u32 + (uint32_t)buf * 20480u;
        const uint32_t sB = sA + 10240u;
#pragma unroll
        for (int i = tid; i < 512; i += 256) {
            const int r = i >> 2, c = i & 3;
            int gm = m0 + r; if (gm >= M) gm = M - 1;
            cp16(sA + (uint32_t)(r * 80 + c * 16), A + (size_t)gm * lda + k0 + c * 8);
            cp16(sB + (uint32_t)(r * 80 + c * 16), B + (size_t)(n0 + r) * ldb + k0 + c * 8);
        }
        asm volatile("cp.async.commit_group;" ::: "memory");
    };

    load_tile(0, 0);

    for (int kt = 0; kt < KT; ++kt) {
        const int cur = kt & 1;
        asm volatile("cp.async.wait_group 0;" ::: "memory");
        __syncthreads();
        if (kt + 1 < KT) load_tile(kt + 1, cur ^ 1);

        const __half* As = ts + cur * 10240;
        const __half* Bs = As + 5120;

#pragma unroll
        for (int ks = 0; ks < 2; ++ks) {
            const int kof = ks * 16 + 2 * t;
            uint32_t av[4][4], bv[4][2];
#pragma unroll
            for (int mt = 0; mt < 4; ++mt) {
                const int row = wm * 64 + mt * 16 + quad;
                av[mt][0] = lds32(As + row * 40 + kof);
                av[mt][1] = lds32(As + (row + 8) * 40 + kof);
                av[mt][2] = lds32(As + row * 40 + kof + 8);
                av[mt][3] = lds32(As + (row + 8) * 40 + kof + 8);
            }
#pragma unroll
            for (int nt = 0; nt < 4; ++nt) {
                const int col = wn * 32 + nt * 8 + quad;
                bv[nt][0] = lds32(Bs + col * 40 + kof);
                bv[nt][1] = lds32(Bs + col * 40 + kof + 8);
            }
#pragma unroll
            for (int mt = 0; mt < 4; ++mt)
#pragma unroll
                for (int nt = 0; nt < 4; ++nt)
                    mma16(acc[mt][nt], av[mt][0], av[mt][1], av[mt][2], av[mt][3],
                          bv[nt][0], bv[nt][1]);
        }
        __syncthreads();
    }

    // epilogue
#pragma unroll
    for (int mt = 0; mt < 4; ++mt) {
        const int r = m0 + wm * 64 + mt * 16 + quad;
#pragma unroll
        for (int nt = 0; nt < 4; ++nt) {
            const int c = n0 + wn * 32 + nt * 8 + 2 * t;
            float v0 = acc[mt][nt][0] * alpha;
            float v1 = acc[mt][nt][1] * alpha;
            float v2 = acc[mt][nt][2] * alpha;
            float v3 = acc[mt][nt][3] * alpha;
            if (bias) {
                const float b0 = bias[c], b1 = bias[c + 1];
                v0 += b0; v1 += b1; v2 += b0; v3 += b1;
            }
            if (OUT16) {
                __half* Ch = (__half*)Cv + (long long)blockIdx.z * zC;
                if (r < M) {
                    uint32_t u = pack2(v0, v1);
                    *(uint32_t*)(Ch + (size_t)r * ldc + c) = u;
                }
                if (r + 8 < M) {
                    uint32_t u = pack2(v2, v3);
                    *(uint32_t*)(Ch + (size_t)(r + 8) * ldc + c) = u;
                }
            } else {
                float* Cf = (float*)Cv + (long long)blockIdx.z * zC;
                if (r < M)
                    *(float2*)(Cf + (size_t)r * ldc + c) = make_float2(v0, v1);
                if (r + 8 < M)
                    *(float2*)(Cf + (size_t)(r + 8) * ldc + c) = make_float2(v2, v3);
            }
        }
    }
}

// ---------------- fused flash attention, fp16 mma ----------------
// grid (108, 8): 128 q-rows x 1 head per CTA, 256 threads (8 warps x 16 rows).
// KV tiles of 96 (18 exact), double-buffered cp.async, fp16 K and V^T in smem.
// smem bytes: K0@0 K1@19968 V0@39936 V1@59904 ; row stride 104 halves (208B).
#define FSMEM16 79872

__global__ __launch_bounds__(256) void flash16(
    const __half* __restrict__ Q, const __half* __restrict__ KV,
    const __half* __restrict__ VT, __half* __restrict__ Out)
{
    extern __shared__ __half fsm[];
    const uint32_t smem_u32 = (uint32_t)__cvta_generic_to_shared(fsm);
    const int h  = blockIdx.y;
    const int q0 = blockIdx.x * 128;
    const int tid = threadIdx.x;
    const int lane = tid & 31, warp = tid >> 5;
    const int quad = lane >> 2, t = lane & 3;
    const int row = warp * 16 + quad;

    // ---- stage Q tile (fp16, already alpha-scaled) into smem, extract A-frags ----
    for (int i = tid; i < 128 * 12; i += 256) {
        const int r = i / 12, c = i % 12;
        cp16(smem_u32 + (uint32_t)(r * 208 + c * 16),
             Q + (size_t)(q0 + r) * C_DIM + h * HD + c * 8);
    }
    asm volatile("cp.async.commit_group;" ::: "memory");
    asm volatile("cp.async.wait_group 0;" ::: "memory");
    __syncthreads();

    uint32_t aQ[6][4];
#pragma unroll
    for (int kc = 0; kc < 6; ++kc) {
        const int kof = kc * 16 + 2 * t;
        aQ[kc][0] = lds32(fsm + row * 104 + kof);
        aQ[kc][1] = lds32(fsm + (row + 8) * 104 + kof);
        aQ[kc][2] = lds32(fsm + row * 104 + kof + 8);
        aQ[kc][3] = lds32(fsm + (row + 8) * 104 + kof + 8);
    }
    __syncthreads();   // Q staging dead; K/V buffers may be written

    auto load_tile = [&](int kvt, int buf) {
        const uint32_t sk = smem_u32 + (uint32_t)buf * 19968u;
        const uint32_t sv = smem_u32 + 39936u + (uint32_t)buf * 19968u;
        const __half* kb = KV + (size_t)(kvt * 96) * (2 * C_DIM) + h * HD;
        const __half* vb = VT + (size_t)(h * HD) * NKV + kvt * 96;
        for (int i = tid; i < 96 * 12; i += 256) {
            const int j = i / 12, c = i % 12;
            cp16(sk + (uint32_t)(j * 208 + c * 16), kb + (size_t)j * (2 * C_DIM) + c * 8);
            cp16(sv + (uint32_t)(j * 208 + c * 16), vb + (size_t)j * NKV + c * 8);
        }
        asm volatile("cp.async.commit_group;" ::: "memory");
    };

    float Oa[12][4];
#pragma unroll
    for (int nf = 0; nf < 12; ++nf) { Oa[nf][0] = Oa[nf][1] = Oa[nf][2] = Oa[nf][3] = 0.f; }
    float m0 = -1e30f, m1 = -1e30f, l0 = 0.f, l1 = 0.f;

    load_tile(0, 0);

    for (int kvt = 0; kvt < 18; ++kvt) {
        const int cur = kvt & 1;
        asm volatile("cp.async.wait_group 0;" ::: "memory");
        __syncthreads();
        if (kvt + 1 < 18) load_tile(kvt + 1, cur ^ 1);

        const __half* Kb = fsm + cur * 9984;            // 19968 B = 9984 halves
        const __half* Vb = fsm + 19968 + cur * 9984;    // 39936 B = 19968 halves

        // ---- S = Q @ K^T  (72 mma) ----
        float s[12][4];
#pragma unroll
        for (int nf = 0; nf < 12; ++nf) { s[nf][0] = s[nf][1] = s[nf][2] = s[nf][3] = 0.f; }
#pragma unroll
        for (int kc = 0; kc < 6; ++kc) {
            const int kof = kc * 16 + 2 * t;
#pragma unroll
            for (int nf = 0; nf < 12; ++nf) {
                const __half* kp = Kb + (nf * 8 + quad) * 104 + kof;
                mma16(s[nf], aQ[kc][0], aQ[kc][1], aQ[kc][2], aQ[kc][3],
                      lds32(kp), lds32(kp + 8));
            }
        }

        // ---- online softmax (rows q and q+8) ----
        float mx0 = -1e30f, mx1 = -1e30f;
#pragma unroll
        for (int nf = 0; nf < 12; ++nf) {
            mx0 = fmaxf(mx0, fmaxf(s[nf][0], s[nf][1]));
            mx1 = fmaxf(mx1, fmaxf(s[nf][2], s[nf][3]));
        }
        mx0 = fmaxf(mx0, __shfl_xor_sync(0xffffffffu, mx0, 1));
        mx0 = fmaxf(mx0, __shfl_xor_sync(0xffffffffu, mx0, 2));
        mx1 = fmaxf(mx1, __shfl_xor_sync(0xffffffffu, mx1, 1));
        mx1 = fmaxf(mx1, __shfl_xor_sync(0xffffffffu, mx1, 2));

        const float mn0 = fmaxf(m0, mx0), mn1 = fmaxf(m1, mx1);
        const float cr0 = __expf(m0 - mn0), cr1 = __expf(m1 - mn1);
        m0 = mn0; m1 = mn1;

        float sum0 = 0.f, sum1 = 0.f;
#pragma unroll
        for (int nf = 0; nf < 12; ++nf) {
            const float p0 = hrnd(__expf(s[nf][0] - mn0));
            const float p1 = hrnd(__expf(s[nf][1] - mn0));
            const float p2 = hrnd(__expf(s[nf][2] - mn1));
            const float p3 = hrnd(__expf(s[nf][3] - mn1));
            s[nf][0] = p0; s[nf][1] = p1; s[nf][2] = p2; s[nf][3] = p3;
            sum0 += p0 + p1; sum1 += p2 + p3;
        }
        sum0 += __shfl_xor_sync(0xffffffffu, sum0, 1);
        sum0 += __shfl_xor_sync(0xffffffffu, sum0, 2);
        sum1 += __shfl_xor_sync(0xffffffffu, sum1, 1);
        sum1 += __shfl_xor_sync(0xffffffffu, sum1, 2);
        l0 = l0 * cr0 + sum0;
        l1 = l1 * cr1 + sum1;

#pragma unroll
        for (int nf = 0; nf < 12; ++nf) {
            Oa[nf][0] *= cr0; Oa[nf][1] *= cr0;
            Oa[nf][2] *= cr1; Oa[nf][3] *= cr1;
        }

        // ---- O += P @ V  (72 mma; A-frags are same-thread register packs) ----
#pragma unroll
        for (int kc = 0; kc < 6; ++kc) {
            const uint32_t a0 = pack2(s[2 * kc][0],     s[2 * kc][1]);
            const uint32_t a1 = pack2(s[2 * kc][2],     s[2 * kc][3]);
            const uint32_t a2 = pack2(s[2 * kc + 1][0], s[2 * kc + 1][1]);
            const uint32_t a3 = pack2(s[2 * kc + 1][2], s[2 * kc + 1][3]);
            const int kof = kc * 16 + 2 * t;
#pragma unroll
            for (int nf = 0; nf < 12; ++nf) {
                const __half* vp = Vb + (nf * 8 + quad) * 104 + kof;
                mma16(Oa[nf], a0, a1, a2, a3, lds32(vp), lds32(vp + 8));
            }
        }
        __syncthreads();   // done reading this buffer before refill
    }

    // ---- normalize + write fp16 ----
    const float inv0 = 1.f / l0, inv1 = 1.f / l1;
    __half* op  = Out + (size_t)(q0 + row) * C_DIM + h * HD + 2 * t;
    __half* op8 = op + 8 * C_DIM;
#pragma unroll
    for (int nf = 0; nf < 12; ++nf) {
        *(uint32_t*)(op  + nf * 8) = pack2(Oa[nf][0] * inv0, Oa[nf][1] * inv0);
        *(uint32_t*)(op8 + nf * 8) = pack2(Oa[nf][2] * inv1, Oa[nf][3] * inv1);
    }
}

// ---------------- prep kernels ----------------
__global__ void cvt16_kernel(const float* __restrict__ s, __half* __restrict__ d, long long n)
{
    const long long i = (long long)blockIdx.x * blockDim.x + threadIdx.x;
    if (i < n) d[i] = __float2half_rn(s[i]);
}

// [K][N] fp32 -> [N][K] fp16   (K, N multiples of 32)
__global__ void trans_cvt16(const float* __restrict__ in, __half* __restrict__ o, int K, int N)
{
    __shared__ float tbuf[32][33];
    const int k0 = blockIdx.y * 32, n0 = blockIdx.x * 32;
    const int tx = threadIdx.x, ty = threadIdx.y;   // 32 x 8
    for (int i = ty; i < 32; i += 8)
        tbuf[i][tx] = in[(size_t)(k0 + i) * N + n0 + tx];
    __syncthreads();
    for (int i = ty; i < 32; i += 8)
        o[(size_t)(n0 + i) * K + k0 + tx] = __float2half_rn(tbuf[tx][i]);
}

// im2col on fp16 x
__global__ void im2col16(const __half* __restrict__ x, __half* __restrict__ col)
{
    const long long idx = (long long)blockIdx.x * blockDim.x + threadIdx.x;
    if (idx >= (long long)NKV * KCONV) return;
    const int p = (int)(idx / KCONV);
    const int r = (int)(idx - (long long)p * KCONV);
    const int ci = r >> 3;
    const int corner = r & 7;
    const int dz = corner >> 2, dy = (corner >> 1) & 1, dx = corner & 1;
    const int pz = p / 144;
    const int rem = p - pz * 144;
    const int py = rem / 12;
    const int px = rem - py * 12;
    const int pos = ((2 * pz + dz) * 24 + (2 * py + dy)) * 24 + (2 * px + dx);
    col[idx] = x[(size_t)pos * C_DIM + ci];
}

// split-K sum + conv bias + LayerNorm -> fp16
__global__ void ln2_16(const float* __restrict__ X0, const float* __restrict__ X1,
                       const float* __restrict__ cb,
                       const float* __restrict__ g, const float* __restrict__ b,
                       __half* __restrict__ Y)
{
    const int r = blockIdx.x;
    const float* r0 = X0 + (size_t)r * C_DIM;
    const float* r1 = X1 + (size_t)r * C_DIM;
    __shared__ float buf[C_DIM];
    __shared__ float s1[256], s2[256];
    const int t = threadIdx.x;
    float sum = 0.f, sq = 0.f;
    for (int i = t; i < C_DIM; i += 256) {
        const float v = r0[i] + r1[i] + cb[i];
        buf[i] = v;
        sum += v; sq += v * v;
    }
    s1[t] = sum; s2[t] = sq;
    __syncthreads();
    for (int st = 128; st > 0; st >>= 1) {
        if (t < st) { s1[t] += s1[t + st]; s2[t] += s2[t + st]; }
        __syncthreads();
    }
    const float mu  = s1[0] * (1.f / C_DIM);
    const float var = s2[0] * (1.f / C_DIM) - mu * mu;
    const float inv = rsqrtf(var + 1e-5f);
    for (int i = t; i < C_DIM; i += 256)
        Y[(size_t)r * C_DIM + i] = __float2half_rn((buf[i] - mu) * inv * g[i] + b[i]);
}

// repack V half of kv into V^T: vt[c][n] = kv[n][768 + c]
__global__ void repack_vt(const __half* __restrict__ kv, __half* __restrict__ vt)
{
    __shared__ __half tbuf[32][33];
    const int n0 = blockIdx.x * 32, c0 = blockIdx.y * 32;
    const int tx = threadIdx.x, ty = threadIdx.y;   // 32 x 8
    for (int i = ty; i < 32; i += 8)
        tbuf[i][tx] = kv[(size_t)(n0 + i) * (2 * C_DIM) + C_DIM + c0 + tx];
    __syncthreads();
    for (int i = ty; i < 32; i += 8)
        vt[(size_t)(c0 + i) * NKV + n0 + tx] = tbuf[tx][i];
}

// ---------------- launch ----------------
extern "C" void kernel_launch(void* const* d_in, const int* in_sizes, int n_in,
                              void* d_out, int out_size)
{
    const float* x      = (const float*)d_in[0];
    const float* wq     = (const float*)d_in[1];
    const float* wkv    = (const float*)d_in[2];
    const float* sr_w   = (const float*)d_in[3];
    const float* sr_b   = (const float*)d_in[4];
    const float* ln_g   = (const float*)d_in[5];
    const float* ln_b   = (const float*)d_in[6];
    const float* proj_w = (const float*)d_in[7];
    const float* proj_b = (const float*)d_in[8];
    float* out = (float*)d_out;

    __half *x16, *wqt, *wkvt, *pjt, *srw, *col16, *q16, *xr16, *kv16, *vt16, *at16;
    float *xr2;
    cudaGetSymbolAddress((void**)&x16,   g_x16);
    cudaGetSymbolAddress((void**)&wqt,   g_wqt);
    cudaGetSymbolAddress((void**)&wkvt,  g_wkvt);
    cudaGetSymbolAddress((void**)&pjt,   g_pjt);
    cudaGetSymbolAddress((void**)&srw,   g_srw);
    cudaGetSymbolAddress((void**)&col16, g_col16);
    cudaGetSymbolAddress((void**)&q16,   g_q16);
    cudaGetSymbolAddress((void**)&xr2,   g_xr2);
    cudaGetSymbolAddress((void**)&xr16,  g_xr16);
    cudaGetSymbolAddress((void**)&kv16,  g_kv16);
    cudaGetSymbolAddress((void**)&vt16,  g_vt16);
    cudaGetSymbolAddress((void**)&at16,  g_at16);

    static int init_done = 0;
    if (!init_done) {
        cudaFuncSetAttribute(flash16,
                             cudaFuncAttributeMaxDynamicSharedMemorySize, FSMEM16);
        init_done = 1;
    }

    const dim3 blk(256);
    const long long nx = (long long)NQ * C_DIM;
    const long long nw = (long long)C_DIM * KCONV;

    // 0) fp16 conversions
    cvt16_kernel<<<(unsigned)((nx + 255) / 256), blk>>>(x, x16, nx);
    cvt16_kernel<<<(unsigned)((nw + 255) / 256), blk>>>(sr_w, srw, nw);
    trans_cvt16<<<dim3(C_DIM / 32, C_DIM / 32), dim3(32, 8)>>>(wq, wqt, C_DIM, C_DIM);
    trans_cvt16<<<dim3(2 * C_DIM / 32, C_DIM / 32), dim3(32, 8)>>>(wkv, wkvt, C_DIM, 2 * C_DIM);
    trans_cvt16<<<dim3(C_DIM / 32, C_DIM / 32), dim3(32, 8)>>>(proj_w, pjt, C_DIM, C_DIM);

    // 1) Q = (x @ wq) * (1/sqrt(8))  -> fp16
    tgemm16<true><<<dim3(6, 108, 1), blk>>>(
        x16, wqt, q16, nullptr, ALPHA_SCORE,
        NQ, C_DIM, C_DIM, C_DIM, C_DIM, C_DIM, 0, 0, 0);

    // 2) im2col (fp16)
    {
        const long long tot = (long long)NKV * KCONV;
        im2col16<<<(unsigned)((tot + 255) / 256), blk>>>(x16, col16);
    }

    // 3) conv-as-GEMM, split-K x2 -> fp32 partials
    tgemm16<false><<<dim3(6, 14, 2), blk>>>(
        col16, srw, xr2, nullptr, 1.f,
        NKV, C_DIM, KCONV / 2, KCONV, KCONV, C_DIM,
        (long long)(KCONV / 2), (long long)(KCONV / 2), (long long)NKV * C_DIM);

    // 4) sum partials + conv bias + LayerNorm -> fp16
    ln2_16<<<NKV, blk>>>(xr2, xr2 + (size_t)NKV * C_DIM, sr_b, ln_g, ln_b, xr16);

    // 5) KV = xr @ wkv -> fp16
    tgemm16<true><<<dim3(12, 14, 1), blk>>>(
        xr16, wkvt, kv16, nullptr, 1.f,
        NKV, 2 * C_DIM, C_DIM, C_DIM, C_DIM, 2 * C_DIM, 0, 0, 0);

    // 5b) V^T repack for flash
    repack_vt<<<dim3(NKV / 32, C_DIM / 32), dim3(32, 8)>>>(kv16, vt16);

    // 6) fused attention -> fp16
    flash16<<<dim3(NQ / 128, NH), blk, FSMEM16>>>(q16, kv16, vt16, at16);

    // 7) out = attn @ proj_w + proj_b  (fp32)
    tgemm16<false><<<dim3(6, 108, 1), blk>>>(
        at16, pjt, out, proj_b, 1.f,
        NQ, C_DIM, C_DIM, C_DIM, C_DIM, C_DIM, 0, 0, 0);
}